// round 14
// baseline (speedup 1.0000x reference)
#include <cuda_runtime.h>
#include <cuda_fp16.h>
#include <cstdint>

#define PSZ (128*128*32)
#define VSZ (64*64*64*8)
#define PCAP (1<<20)          // max points supported by sort path
#define NB   32768            // 32^3 morton buckets

// device scratch
__device__ __align__(128) __half g_plane_h[3*PSZ];   // [p][(row*128+col)*32 + c]
__device__ __align__(128) __half g_vol_h[VSZ];       // [((z*64+y)*64+x)*8 + c]
__device__ __align__(128) float4 g_pts[PCAP];        // sorted (x,y,z,orig_idx)
__device__ unsigned g_cnt[NB];                       // zero-init; re-zeroed by k_scan
__device__ unsigned g_cnt2[NB];

// ---------------- smem byte layout (k_main) ----------------
#define ESTG_OFF  0                    // 8 warps * 2560B plane staging (32 rows x 80B)
#define LINES_OFF 20480                // 3 * 128 * 80B (40 halves/row, 32 used)
#define WBF_OFF   51200                // 3ax*4nt*2kt*32lane*2 uints = 6144B
#define WB1F_OFF  57344                // 16nt*3kt*32lane*2 uints = 12288B
#define VST_OFF   69632                // 8 warps * 32 lanes * 16B = 4096B
#define B1W2_OFF  73728                // 128 * (b1,W2) interleaved f32 = 1024B
#define BAX_OFF   74752                // 3*32 f32 = 384B
#define SMEM_BYTES 75136

// ---------------- morton bucket (32^3, 15-bit) ----------------
__device__ __forceinline__ unsigned mpart5(unsigned v)
{
    v &= 0x1F;
    v = (v | (v << 8)) & 0x0100F;
    v = (v | (v << 4)) & 0x10C3;
    v = (v | (v << 2)) & 0x1249;
    return v;
}
__device__ __forceinline__ unsigned bucket_of(float x, float y, float z)
{
    unsigned bx = (unsigned)min(max((int)((x + 1.f) * 16.f), 0), 31);
    unsigned by = (unsigned)min(max((int)((y + 1.f) * 16.f), 0), 31);
    unsigned bz = (unsigned)min(max((int)((z + 1.f) * 16.f), 0), 31);
    return mpart5(bx) | (mpart5(by) << 1) | (mpart5(bz) << 2);   // 15-bit morton
}

// ---------------- merged preprocessing (transpose + histogram) ----------------
__global__ void k_prep(const float* __restrict__ pxy, const float* __restrict__ pyz,
                       const float* __restrict__ pxz, const float* __restrict__ vol,
                       const float* __restrict__ coords, int M)
{
    int tid = threadIdx.x;
    if (blockIdx.x < 1536) {
        __shared__ float tile[32][33];
        int p   = blockIdx.x >> 9;
        int hw0 = (blockIdx.x & 511) * 32;
        const float* src = (p == 0) ? pxy : (p == 1) ? pyz : pxz;
        __half* dst = g_plane_h + p * PSZ;
        int tx = tid & 31, ty = tid >> 5;
        #pragma unroll
        for (int cc = ty; cc < 32; cc += 8)
            tile[cc][tx] = src[cc * 16384 + hw0 + tx];
        __syncthreads();
        #pragma unroll
        for (int hwL = ty; hwL < 32; hwL += 8)
            dst[(hw0 + hwL) * 32 + tx] = __float2half(tile[tx][hwL]);
    } else if (blockIdx.x < 1536 + 2048) {
        __shared__ float t[8][129];
        int vox0 = (blockIdx.x - 1536) * 128;
        int w = tid >> 5, lane = tid & 31;
        #pragma unroll
        for (int j = lane; j < 128; j += 32)
            t[w][j] = vol[w * 262144 + vox0 + j];
        __syncthreads();
        #pragma unroll
        for (int rep = 0; rep < 4; rep++) {
            int idx = rep * 256 + tid;
            int v = idx >> 3, c = idx & 7;
            g_vol_h[vox0 * 8 + idx] = __float2half(t[c][v]);
        }
    } else {
        int m = (blockIdx.x - (1536 + 2048)) * 256 + tid;
        if (m < M)
            atomicAdd(&g_cnt[bucket_of(coords[3*m], coords[3*m+1], coords[3*m+2])], 1u);
    }
}

// single-block exclusive scan of 32768 buckets (1024 thr x 32 each),
// plus histogram re-zero for the next graph replay.
__global__ void k_scan()
{
    __shared__ unsigned wsum[32];
    int t = threadIdx.x;
    int lane = t & 31, w = t >> 5;

    uint4 v[8];
#pragma unroll
    for (int q = 0; q < 8; q++) v[q] = *(const uint4*)&g_cnt[t*32 + q*4];
    unsigned s = 0;
#pragma unroll
    for (int q = 0; q < 8; q++) s += v[q].x + v[q].y + v[q].z + v[q].w;

    unsigned x = s;
#pragma unroll
    for (int d = 1; d < 32; d <<= 1) {
        unsigned n = __shfl_up_sync(0xffffffffu, x, d);
        if (lane >= d) x += n;
    }
    if (lane == 31) wsum[w] = x;
    __syncthreads();
    if (w == 0) {
        unsigned y = wsum[lane];
        unsigned yx = y;
#pragma unroll
        for (int d = 1; d < 32; d <<= 1) {
            unsigned n = __shfl_up_sync(0xffffffffu, yx, d);
            if (lane >= d) yx += n;
        }
        wsum[lane] = yx - y;
    }
    __syncthreads();

    unsigned run = wsum[w] + (x - s);
    const uint4 z4 = make_uint4(0u, 0u, 0u, 0u);
#pragma unroll
    for (int q = 0; q < 8; q++) {
        uint4 o;
        o.x = run;  run += v[q].x;
        o.y = run;  run += v[q].y;
        o.z = run;  run += v[q].z;
        o.w = run;  run += v[q].w;
        *(uint4*)&g_cnt2[t*32 + q*4] = o;
        *(uint4*)&g_cnt[t*32 + q*4] = z4;   // reset for next replay
    }
}

// scatter: 2 points per thread (ILP on the atomic->store chain)
__global__ void k_scatter(const float* __restrict__ coords, int M)
{
    int m0 = blockIdx.x * 512 + threadIdx.x;
    int m1 = m0 + 256;
    if (m0 < M) {
        float x = coords[3*m0], y = coords[3*m0+1], z = coords[3*m0+2];
        unsigned pos = atomicAdd(&g_cnt2[bucket_of(x, y, z)], 1u);
        __stcs(&g_pts[pos], make_float4(x, y, z, __int_as_float(m0)));
    }
    if (m1 < M) {
        float x = coords[3*m1], y = coords[3*m1+1], z = coords[3*m1+2];
        unsigned pos = atomicAdd(&g_cnt2[bucket_of(x, y, z)], 1u);
        __stcs(&g_pts[pos], make_float4(x, y, z, __int_as_float(m1)));
    }
}

// ---------------- warp MMA helpers ----------------
__device__ __forceinline__ void mma16816(float c[4], const unsigned a[4], const unsigned b[2])
{
    asm volatile("mma.sync.aligned.m16n8k16.row.col.f32.f16.f16.f32 "
        "{%0,%1,%2,%3}, {%4,%5,%6,%7}, {%8,%9}, {%0,%1,%2,%3};\n"
        : "+f"(c[0]), "+f"(c[1]), "+f"(c[2]), "+f"(c[3])
        : "r"(a[0]), "r"(a[1]), "r"(a[2]), "r"(a[3]), "r"(b[0]), "r"(b[1]));
}
__device__ __forceinline__ void mma16808(float c[4], const unsigned a[2], unsigned b)
{
    asm volatile("mma.sync.aligned.m16n8k8.row.col.f32.f16.f16.f32 "
        "{%0,%1,%2,%3}, {%4,%5}, {%6}, {%0,%1,%2,%3};\n"
        : "+f"(c[0]), "+f"(c[1]), "+f"(c[2]), "+f"(c[3])
        : "r"(a[0]), "r"(a[1]), "r"(b));
}
__device__ __forceinline__ void ldsm4(unsigned r[4], unsigned addr)
{
    asm volatile("ldmatrix.sync.aligned.m8n8.x4.shared.b16 {%0,%1,%2,%3}, [%4];"
        : "=r"(r[0]), "=r"(r[1]), "=r"(r[2]), "=r"(r[3]) : "r"(addr));
}
__device__ __forceinline__ unsigned packh2(float a, float b)
{
    __half2 h = __floats2half2_rn(a, b);
    return *(unsigned*)&h;
}

// ---------------- main fused kernel: persistent ----------------
__global__ void __launch_bounds__(256, 2) k_main(
    const float* __restrict__ coords, int use_sorted,
    const float* __restrict__ lx, const float* __restrict__ ly, const float* __restrict__ lz,
    const float* __restrict__ Wx, const float* __restrict__ bx,
    const float* __restrict__ Wy, const float* __restrict__ by,
    const float* __restrict__ Wz, const float* __restrict__ bz,
    const float* __restrict__ W1, const float* __restrict__ b1,
    const float* __restrict__ W2, const float* __restrict__ b2,
    float* __restrict__ out, int M)
{
    extern __shared__ char smem[];
    int tid = threadIdx.x;

    // ---- one-time smem init ----
    {
        __half* Lh = (__half*)(smem + LINES_OFF);
        for (int i = tid; i < 3*4096; i += 256) {
            int ax = i >> 12, r = i & 4095, pos = r >> 5, c = r & 31;
            const float* s = (ax == 0) ? lx : (ax == 1) ? ly : lz;
            Lh[ax*5120 + pos*40 + c] = __float2half(s[c*128 + pos]);
        }
    }
    {
        unsigned* wb = (unsigned*)(smem + WBF_OFF);
        for (int i = tid; i < 1536; i += 256) {
            int ax = i >> 8, r = i & 255;
            int nt = r >> 6, r2 = r & 63, kt = r2 >> 5, ln = r2 & 31;
            int gg = ln >> 2, tt = ln & 3;
            int n = nt*8 + gg, k0 = kt*16 + 2*tt;
            const float* W = (ax == 0) ? Wx : (ax == 1) ? Wy : Wz;
            wb[i*2 + 0] = packh2(W[k0*32 + n],     W[(k0+1)*32 + n]);
            wb[i*2 + 1] = packh2(W[(k0+8)*32 + n], W[(k0+9)*32 + n]);
        }
    }
    {
        unsigned* wb = (unsigned*)(smem + WB1F_OFF);
        for (int i = tid; i < 1536; i += 256) {
            int nt = i / 96, r = i - nt*96, kt = r >> 5, ln = r & 31;
            int gg = ln >> 2, tt = ln & 3;
            int n = nt*8 + gg, k0 = kt*16 + 2*tt;
            float v0 = (k0   < 40) ? W1[(k0  )*128 + n] : 0.f;
            float v1 = (k0+1 < 40) ? W1[(k0+1)*128 + n] : 0.f;
            float v2 = (k0+8 < 40) ? W1[(k0+8)*128 + n] : 0.f;
            float v3 = (k0+9 < 40) ? W1[(k0+9)*128 + n] : 0.f;
            wb[i*2 + 0] = packh2(v0, v1);
            wb[i*2 + 1] = packh2(v2, v3);
        }
    }
    {
        float* ba = (float*)(smem + BAX_OFF);
        for (int i = tid; i < 96; i += 256)
            ba[i] = (i < 32) ? bx[i] : (i < 64) ? by[i-32] : bz[i-64];
        float* s12 = (float*)(smem + B1W2_OFF);
        for (int i = tid; i < 128; i += 256) {
            s12[i*2 + 0] = b1[i];
            s12[i*2 + 1] = W2[i];
        }
    }
    __syncthreads();

    int lane = tid & 31, warp = tid >> 5;
    int g = lane >> 2, t = lane & 3;
    const __half2 z2 = __float2half2_rn(0.f);

    char* eS_base = smem + ESTG_OFF + warp*2560;
    unsigned sbase = (unsigned)__cvta_generic_to_shared(smem);
    unsigned eS_u = sbase + ESTG_OFF + warp*2560;
    int rowpart = (lane & 15)*80 + ((lane >> 4) << 4);
    int lrow = lane & 15;
    int lcolh = (lane >> 4) << 4;
    float bias2 = b2[0];

    int nblk = (M + 255) >> 8;

    for (int blk = blockIdx.x; blk < nblk; blk += gridDim.x) {
        int tile0 = blk * 256 + warp * 32;
        int m  = tile0 + lane;
        int mc = min(m, M - 1);

        float x, y, z;
        int oidx;
        if (use_sorted) {
            float4 p = __ldcs(&g_pts[mc]);
            x = p.x; y = p.y; z = p.z;
            oidx = __float_as_int(p.w);
        } else {
            x = coords[3*mc + 0];
            y = coords[3*mc + 1];
            z = coords[3*mc + 2];
            oidx = mc;
        }

        float fx = (x + 1.f) * (0.5f * 127.f);
        float fy = (y + 1.f) * (0.5f * 127.f);
        float fz = (z + 1.f) * (0.5f * 127.f);
        float fix = fminf(fmaxf(floorf(fx), 0.f), 126.f);
        float fiy = fminf(fmaxf(floorf(fy), 0.f), 126.f);
        float fiz = fminf(fmaxf(floorf(fz), 0.f), 126.f);
        int ix = (int)fix, iy = (int)fiy, iz = (int)fiz;
        float wxp = fx - fix, wyp = fy - fiy, wzp = fz - fiz;

        float gx = (x + 1.f) * (0.5f * 63.f);
        float gy = (y + 1.f) * (0.5f * 63.f);
        float gz = (z + 1.f) * (0.5f * 63.f);
        float gvx = fminf(fmaxf(floorf(gx), 0.f), 62.f);
        float gvy = fminf(fmaxf(floorf(gy), 0.f), 62.f);
        float gvz = fminf(fmaxf(floorf(gz), 0.f), 62.f);
        int vx = (int)gvx, vy = (int)gvy, vz = (int)gvz;
        float ux = gx - gvx, uy = gy - gvy, uz = gz - gvz;

        // ---- volume trilinear -> VST ----
        {
            const uint4* vb = (const uint4*)(g_vol_h + ((((vz*64 + vy)*64) + vx) << 3));
            float iux = 1.f - ux, iuy = 1.f - uy, iuz = 1.f - uz;
            __half2 va0 = z2, va1 = z2, va2 = z2, va3 = z2;
#pragma unroll
            for (int corner = 0; corner < 8; corner++) {
                int dx = corner & 1, dy = (corner >> 1) & 1, dz = corner >> 2;
                float wgt = (dx ? ux : iux) * (dy ? uy : iuy) * (dz ? uz : iuz);
                __half2 w2 = __float2half2_rn(wgt);
                uint4 T = vb[dx + dy*64 + dz*4096];
                const __half2* th = (const __half2*)&T;
                va0 = __hfma2(w2, th[0], va0);
                va1 = __hfma2(w2, th[1], va1);
                va2 = __hfma2(w2, th[2], va2);
                va3 = __hfma2(w2, th[3], va3);
            }
            uint4* vr = (uint4*)(smem + VST_OFF + warp*512 + lane*16);
            uint4 o;
            o.x = *(unsigned*)&va0; o.y = *(unsigned*)&va1;
            o.z = *(unsigned*)&va2; o.w = *(unsigned*)&va3;
            *vr = o;
        }

        int ixs[3] = { ix, iy, iz };
        float wls[3] = { wxp, wyp, wzp };
        const __half* plb[3] = { g_plane_h + PSZ, g_plane_h + 2*PSZ, g_plane_h };
        int pcol[3] = { iy, ix, ix };
        int prow[3] = { iz, iz, iy };
        float pwc[3] = { wyp, wxp, wxp };
        float pwr[3] = { wzp, wzp, wyp };

        float feat[2][4][4];

#pragma unroll
        for (int ax = 0; ax < 3; ax++) {
            unsigned aL[2][2][4], aP[2][2][4];

            // ---- plane sample (issues LDGs early) -> staging rows ----
            {
                const uint4* t00 = (const uint4*)(plb[ax] + (size_t)(prow[ax]*128 + pcol[ax])*32);
                const uint4* t01 = t00 + 4;
                const uint4* t10 = t00 + 512;
                const uint4* t11 = t10 + 4;
                float wc = pwc[ax], wr = pwr[ax];
                float iwc = 1.f - wc, iwr = 1.f - wr;
                __half2 w00 = __float2half2_rn(iwc*iwr);
                __half2 w01 = __float2half2_rn( wc*iwr);
                __half2 w10 = __float2half2_rn(iwc* wr);
                __half2 w11 = __float2half2_rn( wc* wr);
                uint4* dst = (uint4*)(eS_base + lane*80);
#pragma unroll
                for (int h = 0; h < 4; h++) {
                    uint4 A = t00[h], B = t01[h], C = t10[h], D = t11[h];
                    const __half2* a = (const __half2*)&A;
                    const __half2* b = (const __half2*)&B;
                    const __half2* c = (const __half2*)&C;
                    const __half2* d = (const __half2*)&D;
                    uint4 o;
                    unsigned* oh = (unsigned*)&o;
#pragma unroll
                    for (int k = 0; k < 4; k++) {
                        __half2 acc = __hmul2(w00, a[k]);
                        __half2 ac2 = __hmul2(w01, b[k]);
                        acc = __hfma2(w10, c[k], acc);
                        ac2 = __hfma2(w11, d[k], ac2);
                        acc = __hadd2(acc, ac2);
                        acc = __hmax2(acc, z2);
                        oh[k] = *(unsigned*)&acc;
                    }
                    dst[h] = o;
                }
            }

            // ---- line A-fragments direct from LINES via ldmatrix ----
            {
                unsigned lines_u = sbase + LINES_OFF + ax*10240;
#pragma unroll
                for (int mt = 0; mt < 2; mt++) {
                    int   ixv = __shfl_sync(0xffffffffu, ixs[ax], mt*16 + lrow);
                    float wA  = __shfl_sync(0xffffffffu, wls[ax], mt*16 + g);
                    float wB  = __shfl_sync(0xffffffffu, wls[ax], mt*16 + g + 8);
                    __half2 wA2 = __float2half2_rn(wA);
                    __half2 wB2 = __float2half2_rn(wB);
                    unsigned base0 = lines_u + ixv*80 + lcolh;
#pragma unroll
                    for (int kt = 0; kt < 2; kt++) {
                        unsigned r0[4], r1[4];
                        ldsm4(r0, base0 + kt*32);
                        ldsm4(r1, base0 + 80 + kt*32);
#pragma unroll
                        for (int j = 0; j < 4; j++) {
                            __half2 l0 = *(__half2*)&r0[j];
                            __half2 l1 = *(__half2*)&r1[j];
                            __half2 w2 = (j & 1) ? wB2 : wA2;
                            __half2 e  = __hfma2(w2, __hsub2(l1, l0), l0);
                            e = __hmax2(e, z2);
                            aL[mt][kt][j] = *(unsigned*)&e;
                        }
                    }
                }
            }

            __syncwarp();
#pragma unroll
            for (int mt = 0; mt < 2; mt++)
#pragma unroll
            for (int kt = 0; kt < 2; kt++)
                ldsm4(aP[mt][kt], eS_u + mt*16*80 + kt*32 + rowpart);
            __syncwarp();

            const unsigned* wb = (const unsigned*)(smem + WBF_OFF) + ax*512;
            const float* ba = (const float*)(smem + BAX_OFF) + ax*32;
#pragma unroll
            for (int nt = 0; nt < 4; nt++) {
                uint2 bfa = *(const uint2*)(wb + ((nt*2+0)*32 + lane)*2);
                uint2 bfb = *(const uint2*)(wb + ((nt*2+1)*32 + lane)*2);
                unsigned bf0[2] = { bfa.x, bfa.y };
                unsigned bf1[2] = { bfb.x, bfb.y };
                float2 bb = *(const float2*)(ba + nt*8 + 2*t);
#pragma unroll
                for (int mt = 0; mt < 2; mt++) {
                    float tl[4] = {0.f,0.f,0.f,0.f};
                    float tp[4] = {0.f,0.f,0.f,0.f};
                    mma16816(tl, aL[mt][0], bf0);
                    mma16816(tl, aL[mt][1], bf1);
                    mma16816(tp, aP[mt][0], bf0);
                    mma16816(tp, aP[mt][1], bf1);
                    float v0 = (tl[0] + bb.x) * (tp[0] + bb.x);
                    float v1 = (tl[1] + bb.y) * (tp[1] + bb.y);
                    float v2 = (tl[2] + bb.x) * (tp[2] + bb.x);
                    float v3 = (tl[3] + bb.y) * (tp[3] + bb.y);
                    if (ax == 0) {
                        feat[mt][nt][0] = v0; feat[mt][nt][1] = v1;
                        feat[mt][nt][2] = v2; feat[mt][nt][3] = v3;
                    } else {
                        feat[mt][nt][0] += v0; feat[mt][nt][1] += v1;
                        feat[mt][nt][2] += v2; feat[mt][nt][3] += v3;
                    }
                }
            }
        }

        // ---- MLP A fragments: feat (k16 x2) + vol (k8) ----
        unsigned aM[2][2][4], aMv[2][2];
        const unsigned* vst = (const unsigned*)(smem + VST_OFF + warp*512);
#pragma unroll
        for (int mt = 0; mt < 2; mt++) {
#pragma unroll
            for (int kt = 0; kt < 2; kt++) {
                aM[mt][kt][0] = packh2(feat[mt][2*kt][0],   feat[mt][2*kt][1]);
                aM[mt][kt][1] = packh2(feat[mt][2*kt][2],   feat[mt][2*kt][3]);
                aM[mt][kt][2] = packh2(feat[mt][2*kt+1][0], feat[mt][2*kt+1][1]);
                aM[mt][kt][3] = packh2(feat[mt][2*kt+1][2], feat[mt][2*kt+1][3]);
            }
            aMv[mt][0] = vst[(mt*16 + g)*4 + t];
            aMv[mt][1] = vst[(mt*16 + g + 8)*4 + t];
        }

        // ---- MLP MMAs + fused relu + W2 dot ----
        float s0[2] = {0.f, 0.f}, s1[2] = {0.f, 0.f};
        const unsigned* wb1 = (const unsigned*)(smem + WB1F_OFF);
        const float* s12 = (const float*)(smem + B1W2_OFF);
#pragma unroll
        for (int nt = 0; nt < 16; nt++) {
            uint2 v0 = *(const uint2*)(wb1 + ((nt*3 + 0)*32 + lane)*2);
            uint2 v1 = *(const uint2*)(wb1 + ((nt*3 + 1)*32 + lane)*2);
            unsigned bv = wb1[((nt*3 + 2)*32 + lane)*2];
            unsigned bf0[2] = { v0.x, v0.y };
            unsigned bf1[2] = { v1.x, v1.y };
            float4 f12 = *(const float4*)(s12 + (nt*8 + 2*t)*2);
#pragma unroll
            for (int mt = 0; mt < 2; mt++) {
                float c[4] = {0.f,0.f,0.f,0.f};
                mma16816(c, aM[mt][0], bf0);
                mma16816(c, aM[mt][1], bf1);
                mma16808(c, aMv[mt], bv);
                s0[mt] += fmaxf(c[0] + f12.x, 0.f)*f12.y + fmaxf(c[1] + f12.z, 0.f)*f12.w;
                s1[mt] += fmaxf(c[2] + f12.x, 0.f)*f12.y + fmaxf(c[3] + f12.z, 0.f)*f12.w;
            }
        }

        // ---- quad reduce + scatter store via original index ----
#pragma unroll
        for (int mt = 0; mt < 2; mt++) {
            s0[mt] += __shfl_xor_sync(0xffffffffu, s0[mt], 1);
            s0[mt] += __shfl_xor_sync(0xffffffffu, s0[mt], 2);
            s1[mt] += __shfl_xor_sync(0xffffffffu, s1[mt], 1);
            s1[mt] += __shfl_xor_sync(0xffffffffu, s1[mt], 2);
        }
#pragma unroll
        for (int mt = 0; mt < 2; mt++) {
            int r0 = mt*16 + g, r1 = r0 + 8;
            int i0 = __shfl_sync(0xffffffffu, oidx, r0);
            int i1 = __shfl_sync(0xffffffffu, oidx, r1);
            if (t == 0) {
                if (tile0 + r0 < M) out[i0] = s0[mt] + bias2;
                if (tile0 + r1 < M) out[i1] = s1[mt] + bias2;
            }
        }
        __syncwarp();
    }
}

// ---------------- launch ----------------
extern "C" void kernel_launch(void* const* d_in, const int* in_sizes, int n_in,
                              void* d_out, int out_size)
{
    const float* coords = (const float*)d_in[0];
    const float* lx  = (const float*)d_in[1];
    const float* ly  = (const float*)d_in[2];
    const float* lz  = (const float*)d_in[3];
    const float* pxy = (const float*)d_in[4];
    const float* pyz = (const float*)d_in[5];
    const float* pxz = (const float*)d_in[6];
    const float* vol = (const float*)d_in[7];
    const float* Wx  = (const float*)d_in[8];
    const float* bx  = (const float*)d_in[9];
    const float* Wy  = (const float*)d_in[10];
    const float* by  = (const float*)d_in[11];
    const float* Wz  = (const float*)d_in[12];
    const float* bz  = (const float*)d_in[13];
    const float* W1  = (const float*)d_in[14];
    const float* b1  = (const float*)d_in[15];
    const float* W2  = (const float*)d_in[16];
    const float* b2  = (const float*)d_in[17];
    float* out = (float*)d_out;

    int M = in_sizes[0] / 3;
    int use_sorted = (M > 0 && M <= PCAP) ? 1 : 0;
    int gp = (M + 255) / 256;

    cudaFuncSetAttribute(k_main, cudaFuncAttributeMaxDynamicSharedMemorySize, SMEM_BYTES);

    if (use_sorted) {
        // g_cnt arrives zeroed: static zero-init on first run, re-zeroed by k_scan each replay
        k_prep<<<1536 + 2048 + gp, 256>>>(pxy, pyz, pxz, vol, coords, M);
        k_scan<<<1, 1024>>>();
        k_scatter<<<(M + 511) / 512, 256>>>(coords, M);
    } else {
        k_prep<<<1536 + 2048, 256>>>(pxy, pyz, pxz, vol, coords, 0);
    }

    int grid = min(296, gp);
    k_main<<<grid, 256, SMEM_BYTES>>>(coords, use_sorted, lx, ly, lz,
                                      Wx, bx, Wy, by, Wz, bz,
                                      W1, b1, W2, b2, out, M);
}

// round 15
// speedup vs baseline: 1.1371x; 1.1371x over previous
#include <cuda_runtime.h>
#include <cuda_fp16.h>
#include <cstdint>

#define PSZ (128*128*32)
#define VSZ (64*64*64*8)
#define PCAP (1<<20)          // max points supported by sort path
#define NB   262144           // 64^3 morton buckets

// device scratch
__device__ __align__(128) __half g_plane_h[3*PSZ];   // [p][(row*128+col)*32 + c]
__device__ __align__(128) __half g_vol_h[VSZ];       // [((z*64+y)*64+x)*8 + c]
__device__ __align__(128) float4 g_pts[PCAP];        // sorted (x,y,z,orig_idx)
__device__ unsigned g_cnt[NB];                       // zero-init; re-zeroed by k_scanC
__device__ unsigned g_cnt2[NB];
__device__ unsigned g_bsum[256];

// ---------------- smem byte layout (k_main) ----------------
#define ESTG_OFF  0                    // 8 warps * 2560B plane staging (32 rows x 80B)
#define LINES_OFF 20480                // 3 * 128 * 80B (40 halves/row, 32 used)
#define WBF_OFF   51200                // 3ax*4nt*2kt*32lane*2 uints = 6144B
#define WB1F_OFF  57344                // 16nt*3kt*32lane*2 uints = 12288B
#define VST_OFF   69632                // 8 warps * 32 lanes * 16B = 4096B
#define B1W2_OFF  73728                // 128 * (b1,W2) interleaved f32 = 1024B
#define BAX_OFF   74752                // 3*32 f32 = 384B
#define SMEM_BYTES 75136

// ---------------- morton bucket (64^3, 18-bit) ----------------
__device__ __forceinline__ unsigned mpart(unsigned v)
{
    v &= 0x3FF;
    v = (v | (v << 16)) & 0x030000FF;
    v = (v | (v << 8))  & 0x0300F00F;
    v = (v | (v << 4))  & 0x030C30C3;
    v = (v | (v << 2))  & 0x09249249;
    return v;
}
__device__ __forceinline__ unsigned bucket_of(float x, float y, float z)
{
    unsigned bx = (unsigned)min(max((int)((x + 1.f) * 32.f), 0), 63);
    unsigned by = (unsigned)min(max((int)((y + 1.f) * 32.f), 0), 63);
    unsigned bz = (unsigned)min(max((int)((z + 1.f) * 32.f), 0), 63);
    return mpart(bx) | (mpart(by) << 1) | (mpart(bz) << 2);   // 18-bit morton
}

// ---------------- merged preprocessing (transpose + histogram) ----------------
__global__ void k_prep(const float* __restrict__ pxy, const float* __restrict__ pyz,
                       const float* __restrict__ pxz, const float* __restrict__ vol,
                       const float* __restrict__ coords, int M)
{
    int tid = threadIdx.x;
    if (blockIdx.x < 1536) {
        __shared__ float tile[32][33];
        int p   = blockIdx.x >> 9;
        int hw0 = (blockIdx.x & 511) * 32;
        const float* src = (p == 0) ? pxy : (p == 1) ? pyz : pxz;
        __half* dst = g_plane_h + p * PSZ;
        int tx = tid & 31, ty = tid >> 5;
        #pragma unroll
        for (int cc = ty; cc < 32; cc += 8)
            tile[cc][tx] = src[cc * 16384 + hw0 + tx];
        __syncthreads();
        #pragma unroll
        for (int hwL = ty; hwL < 32; hwL += 8)
            dst[(hw0 + hwL) * 32 + tx] = __float2half(tile[tx][hwL]);
    } else if (blockIdx.x < 1536 + 2048) {
        __shared__ float t[8][129];
        int vox0 = (blockIdx.x - 1536) * 128;
        int w = tid >> 5, lane = tid & 31;
        #pragma unroll
        for (int j = lane; j < 128; j += 32)
            t[w][j] = vol[w * 262144 + vox0 + j];
        __syncthreads();
        #pragma unroll
        for (int rep = 0; rep < 4; rep++) {
            int idx = rep * 256 + tid;
            int v = idx >> 3, c = idx & 7;
            g_vol_h[vox0 * 8 + idx] = __float2half(t[c][v]);
        }
    } else {
        int m = (blockIdx.x - (1536 + 2048)) * 256 + tid;
        if (m < M)
            atomicAdd(&g_cnt[bucket_of(coords[3*m], coords[3*m+1], coords[3*m+2])], 1u);
    }
}

// ---------------- 2-stage parallel scan of 262144 buckets ----------------
// stage A: 256 blocks x 256 threads; each block sums 1024 buckets
__global__ void k_scanA()
{
    __shared__ unsigned red[256];
    int b = blockIdx.x, t = threadIdx.x;
    uint4 v = *(const uint4*)&g_cnt[b*1024 + t*4];
    red[t] = v.x + v.y + v.z + v.w;
    __syncthreads();
    for (int d = 128; d > 0; d >>= 1) {
        if (t < d) red[t] += red[t + d];
        __syncthreads();
    }
    if (t == 0) g_bsum[b] = red[0];
}

// stage C: 256 blocks; computes own global offset from g_bsum, local exclusive
// scan, writes g_cnt2, and re-zeroes g_cnt for the next graph replay.
__global__ void k_scanC()
{
    __shared__ unsigned ss[256];
    __shared__ unsigned pre[256];
    int b = blockIdx.x, t = threadIdx.x;

    pre[t] = (t < b) ? g_bsum[t] : 0u;
    uint4 v = *(const uint4*)&g_cnt[b*1024 + t*4];
    unsigned s = v.x + v.y + v.z + v.w;
    ss[t] = s;
    __syncthreads();
    for (int d = 128; d > 0; d >>= 1) {
        if (t < d) pre[t] += pre[t + d];
        __syncthreads();
    }
    unsigned blk_off = pre[0];
    __syncthreads();
    for (int d = 1; d < 256; d <<= 1) {
        unsigned add = (t >= d) ? ss[t - d] : 0u;
        __syncthreads();
        ss[t] += add;
        __syncthreads();
    }
    unsigned excl = ss[t] - s + blk_off;
    uint4 o;
    o.x = excl;
    o.y = excl + v.x;
    o.z = excl + v.x + v.y;
    o.w = excl + v.x + v.y + v.z;
    *(uint4*)&g_cnt2[b*1024 + t*4] = o;

    uint4 z = make_uint4(0u, 0u, 0u, 0u);
    *(uint4*)&g_cnt[b*1024 + t*4] = z;
}

// scatter: 2 points per thread (ILP on the atomic->store chain)
__global__ void k_scatter(const float* __restrict__ coords, int M)
{
    int m0 = blockIdx.x * 512 + threadIdx.x;
    int m1 = m0 + 256;
    if (m0 < M) {
        float x = coords[3*m0], y = coords[3*m0+1], z = coords[3*m0+2];
        unsigned pos = atomicAdd(&g_cnt2[bucket_of(x, y, z)], 1u);
        __stcs(&g_pts[pos], make_float4(x, y, z, __int_as_float(m0)));
    }
    if (m1 < M) {
        float x = coords[3*m1], y = coords[3*m1+1], z = coords[3*m1+2];
        unsigned pos = atomicAdd(&g_cnt2[bucket_of(x, y, z)], 1u);
        __stcs(&g_pts[pos], make_float4(x, y, z, __int_as_float(m1)));
    }
}

// ---------------- warp MMA helpers ----------------
__device__ __forceinline__ void mma16816(float c[4], const unsigned a[4], const unsigned b[2])
{
    asm volatile("mma.sync.aligned.m16n8k16.row.col.f32.f16.f16.f32 "
        "{%0,%1,%2,%3}, {%4,%5,%6,%7}, {%8,%9}, {%0,%1,%2,%3};\n"
        : "+f"(c[0]), "+f"(c[1]), "+f"(c[2]), "+f"(c[3])
        : "r"(a[0]), "r"(a[1]), "r"(a[2]), "r"(a[3]), "r"(b[0]), "r"(b[1]));
}
__device__ __forceinline__ void mma16808(float c[4], const unsigned a[2], unsigned b)
{
    asm volatile("mma.sync.aligned.m16n8k8.row.col.f32.f16.f16.f32 "
        "{%0,%1,%2,%3}, {%4,%5}, {%6}, {%0,%1,%2,%3};\n"
        : "+f"(c[0]), "+f"(c[1]), "+f"(c[2]), "+f"(c[3])
        : "r"(a[0]), "r"(a[1]), "r"(b));
}
__device__ __forceinline__ void ldsm4(unsigned r[4], unsigned addr)
{
    asm volatile("ldmatrix.sync.aligned.m8n8.x4.shared.b16 {%0,%1,%2,%3}, [%4];"
        : "=r"(r[0]), "=r"(r[1]), "=r"(r[2]), "=r"(r[3]) : "r"(addr));
}
__device__ __forceinline__ unsigned packh2(float a, float b)
{
    __half2 h = __floats2half2_rn(a, b);
    return *(unsigned*)&h;
}

// ---------------- main fused kernel: persistent ----------------
__global__ void __launch_bounds__(256, 2) k_main(
    const float* __restrict__ coords, int use_sorted,
    const float* __restrict__ lx, const float* __restrict__ ly, const float* __restrict__ lz,
    const float* __restrict__ Wx, const float* __restrict__ bx,
    const float* __restrict__ Wy, const float* __restrict__ by,
    const float* __restrict__ Wz, const float* __restrict__ bz,
    const float* __restrict__ W1, const float* __restrict__ b1,
    const float* __restrict__ W2, const float* __restrict__ b2,
    float* __restrict__ out, int M)
{
    extern __shared__ char smem[];
    int tid = threadIdx.x;

    // ---- one-time smem init ----
    {
        __half* Lh = (__half*)(smem + LINES_OFF);
        for (int i = tid; i < 3*4096; i += 256) {
            int ax = i >> 12, r = i & 4095, pos = r >> 5, c = r & 31;
            const float* s = (ax == 0) ? lx : (ax == 1) ? ly : lz;
            Lh[ax*5120 + pos*40 + c] = __float2half(s[c*128 + pos]);
        }
    }
    {
        unsigned* wb = (unsigned*)(smem + WBF_OFF);
        for (int i = tid; i < 1536; i += 256) {
            int ax = i >> 8, r = i & 255;
            int nt = r >> 6, r2 = r & 63, kt = r2 >> 5, ln = r2 & 31;
            int gg = ln >> 2, tt = ln & 3;
            int n = nt*8 + gg, k0 = kt*16 + 2*tt;
            const float* W = (ax == 0) ? Wx : (ax == 1) ? Wy : Wz;
            wb[i*2 + 0] = packh2(W[k0*32 + n],     W[(k0+1)*32 + n]);
            wb[i*2 + 1] = packh2(W[(k0+8)*32 + n], W[(k0+9)*32 + n]);
        }
    }
    {
        unsigned* wb = (unsigned*)(smem + WB1F_OFF);
        for (int i = tid; i < 1536; i += 256) {
            int nt = i / 96, r = i - nt*96, kt = r >> 5, ln = r & 31;
            int gg = ln >> 2, tt = ln & 3;
            int n = nt*8 + gg, k0 = kt*16 + 2*tt;
            float v0 = (k0   < 40) ? W1[(k0  )*128 + n] : 0.f;
            float v1 = (k0+1 < 40) ? W1[(k0+1)*128 + n] : 0.f;
            float v2 = (k0+8 < 40) ? W1[(k0+8)*128 + n] : 0.f;
            float v3 = (k0+9 < 40) ? W1[(k0+9)*128 + n] : 0.f;
            wb[i*2 + 0] = packh2(v0, v1);
            wb[i*2 + 1] = packh2(v2, v3);
        }
    }
    {
        float* ba = (float*)(smem + BAX_OFF);
        for (int i = tid; i < 96; i += 256)
            ba[i] = (i < 32) ? bx[i] : (i < 64) ? by[i-32] : bz[i-64];
        float* s12 = (float*)(smem + B1W2_OFF);
        for (int i = tid; i < 128; i += 256) {
            s12[i*2 + 0] = b1[i];
            s12[i*2 + 1] = W2[i];
        }
    }
    __syncthreads();

    int lane = tid & 31, warp = tid >> 5;
    int g = lane >> 2, t = lane & 3;
    const __half2 z2 = __float2half2_rn(0.f);

    char* eS_base = smem + ESTG_OFF + warp*2560;
    unsigned sbase = (unsigned)__cvta_generic_to_shared(smem);
    unsigned eS_u = sbase + ESTG_OFF + warp*2560;
    int rowpart = (lane & 15)*80 + ((lane >> 4) << 4);
    int lrow = lane & 15;
    int lcolh = (lane >> 4) << 4;
    float bias2 = b2[0];

    int nblk = (M + 255) >> 8;

    for (int blk = blockIdx.x; blk < nblk; blk += gridDim.x) {
        int tile0 = blk * 256 + warp * 32;
        int m  = tile0 + lane;
        int mc = min(m, M - 1);

        float x, y, z;
        int oidx;
        if (use_sorted) {
            float4 p = __ldcs(&g_pts[mc]);
            x = p.x; y = p.y; z = p.z;
            oidx = __float_as_int(p.w);
        } else {
            x = coords[3*mc + 0];
            y = coords[3*mc + 1];
            z = coords[3*mc + 2];
            oidx = mc;
        }

        float fx = (x + 1.f) * (0.5f * 127.f);
        float fy = (y + 1.f) * (0.5f * 127.f);
        float fz = (z + 1.f) * (0.5f * 127.f);
        float fix = fminf(fmaxf(floorf(fx), 0.f), 126.f);
        float fiy = fminf(fmaxf(floorf(fy), 0.f), 126.f);
        float fiz = fminf(fmaxf(floorf(fz), 0.f), 126.f);
        int ix = (int)fix, iy = (int)fiy, iz = (int)fiz;
        float wxp = fx - fix, wyp = fy - fiy, wzp = fz - fiz;

        float gx = (x + 1.f) * (0.5f * 63.f);
        float gy = (y + 1.f) * (0.5f * 63.f);
        float gz = (z + 1.f) * (0.5f * 63.f);
        float gvx = fminf(fmaxf(floorf(gx), 0.f), 62.f);
        float gvy = fminf(fmaxf(floorf(gy), 0.f), 62.f);
        float gvz = fminf(fmaxf(floorf(gz), 0.f), 62.f);
        int vx = (int)gvx, vy = (int)gvy, vz = (int)gvz;
        float ux = gx - gvx, uy = gy - gvy, uz = gz - gvz;

        // ---- volume trilinear -> VST ----
        {
            const uint4* vb = (const uint4*)(g_vol_h + ((((vz*64 + vy)*64) + vx) << 3));
            float iux = 1.f - ux, iuy = 1.f - uy, iuz = 1.f - uz;
            __half2 va0 = z2, va1 = z2, va2 = z2, va3 = z2;
#pragma unroll
            for (int corner = 0; corner < 8; corner++) {
                int dx = corner & 1, dy = (corner >> 1) & 1, dz = corner >> 2;
                float wgt = (dx ? ux : iux) * (dy ? uy : iuy) * (dz ? uz : iuz);
                __half2 w2 = __float2half2_rn(wgt);
                uint4 T = vb[dx + dy*64 + dz*4096];
                const __half2* th = (const __half2*)&T;
                va0 = __hfma2(w2, th[0], va0);
                va1 = __hfma2(w2, th[1], va1);
                va2 = __hfma2(w2, th[2], va2);
                va3 = __hfma2(w2, th[3], va3);
            }
            uint4* vr = (uint4*)(smem + VST_OFF + warp*512 + lane*16);
            uint4 o;
            o.x = *(unsigned*)&va0; o.y = *(unsigned*)&va1;
            o.z = *(unsigned*)&va2; o.w = *(unsigned*)&va3;
            *vr = o;
        }

        int ixs[3] = { ix, iy, iz };
        float wls[3] = { wxp, wyp, wzp };
        const __half* plb[3] = { g_plane_h + PSZ, g_plane_h + 2*PSZ, g_plane_h };
        int pcol[3] = { iy, ix, ix };
        int prow[3] = { iz, iz, iy };
        float pwc[3] = { wyp, wxp, wxp };
        float pwr[3] = { wzp, wzp, wyp };

        float feat[2][4][4];

#pragma unroll
        for (int ax = 0; ax < 3; ax++) {
            unsigned aL[2][2][4], aP[2][2][4];

            // ---- plane sample (issues LDGs early) -> staging rows ----
            {
                const uint4* t00 = (const uint4*)(plb[ax] + (size_t)(prow[ax]*128 + pcol[ax])*32);
                const uint4* t01 = t00 + 4;
                const uint4* t10 = t00 + 512;
                const uint4* t11 = t10 + 4;
                float wc = pwc[ax], wr = pwr[ax];
                float iwc = 1.f - wc, iwr = 1.f - wr;
                __half2 w00 = __float2half2_rn(iwc*iwr);
                __half2 w01 = __float2half2_rn( wc*iwr);
                __half2 w10 = __float2half2_rn(iwc* wr);
                __half2 w11 = __float2half2_rn( wc* wr);
                uint4* dst = (uint4*)(eS_base + lane*80);
#pragma unroll
                for (int h = 0; h < 4; h++) {
                    uint4 A = t00[h], B = t01[h], C = t10[h], D = t11[h];
                    const __half2* a = (const __half2*)&A;
                    const __half2* b = (const __half2*)&B;
                    const __half2* c = (const __half2*)&C;
                    const __half2* d = (const __half2*)&D;
                    uint4 o;
                    unsigned* oh = (unsigned*)&o;
#pragma unroll
                    for (int k = 0; k < 4; k++) {
                        __half2 acc = __hmul2(w00, a[k]);
                        __half2 ac2 = __hmul2(w01, b[k]);
                        acc = __hfma2(w10, c[k], acc);
                        ac2 = __hfma2(w11, d[k], ac2);
                        acc = __hadd2(acc, ac2);
                        acc = __hmax2(acc, z2);
                        oh[k] = *(unsigned*)&acc;
                    }
                    dst[h] = o;
                }
            }

            // ---- line A-fragments direct from LINES via ldmatrix ----
            {
                unsigned lines_u = sbase + LINES_OFF + ax*10240;
#pragma unroll
                for (int mt = 0; mt < 2; mt++) {
                    int   ixv = __shfl_sync(0xffffffffu, ixs[ax], mt*16 + lrow);
                    float wA  = __shfl_sync(0xffffffffu, wls[ax], mt*16 + g);
                    float wB  = __shfl_sync(0xffffffffu, wls[ax], mt*16 + g + 8);
                    __half2 wA2 = __float2half2_rn(wA);
                    __half2 wB2 = __float2half2_rn(wB);
                    unsigned base0 = lines_u + ixv*80 + lcolh;
#pragma unroll
                    for (int kt = 0; kt < 2; kt++) {
                        unsigned r0[4], r1[4];
                        ldsm4(r0, base0 + kt*32);
                        ldsm4(r1, base0 + 80 + kt*32);
#pragma unroll
                        for (int j = 0; j < 4; j++) {
                            __half2 l0 = *(__half2*)&r0[j];
                            __half2 l1 = *(__half2*)&r1[j];
                            __half2 w2 = (j & 1) ? wB2 : wA2;
                            __half2 e  = __hfma2(w2, __hsub2(l1, l0), l0);
                            e = __hmax2(e, z2);
                            aL[mt][kt][j] = *(unsigned*)&e;
                        }
                    }
                }
            }

            __syncwarp();
#pragma unroll
            for (int mt = 0; mt < 2; mt++)
#pragma unroll
            for (int kt = 0; kt < 2; kt++)
                ldsm4(aP[mt][kt], eS_u + mt*16*80 + kt*32 + rowpart);
            __syncwarp();

            const unsigned* wb = (const unsigned*)(smem + WBF_OFF) + ax*512;
            const float* ba = (const float*)(smem + BAX_OFF) + ax*32;
#pragma unroll
            for (int nt = 0; nt < 4; nt++) {
                uint2 bfa = *(const uint2*)(wb + ((nt*2+0)*32 + lane)*2);
                uint2 bfb = *(const uint2*)(wb + ((nt*2+1)*32 + lane)*2);
                unsigned bf0[2] = { bfa.x, bfa.y };
                unsigned bf1[2] = { bfb.x, bfb.y };
                float2 bb = *(const float2*)(ba + nt*8 + 2*t);
#pragma unroll
                for (int mt = 0; mt < 2; mt++) {
                    float tl[4] = {0.f,0.f,0.f,0.f};
                    float tp[4] = {0.f,0.f,0.f,0.f};
                    mma16816(tl, aL[mt][0], bf0);
                    mma16816(tl, aL[mt][1], bf1);
                    mma16816(tp, aP[mt][0], bf0);
                    mma16816(tp, aP[mt][1], bf1);
                    float v0 = (tl[0] + bb.x) * (tp[0] + bb.x);
                    float v1 = (tl[1] + bb.y) * (tp[1] + bb.y);
                    float v2 = (tl[2] + bb.x) * (tp[2] + bb.x);
                    float v3 = (tl[3] + bb.y) * (tp[3] + bb.y);
                    if (ax == 0) {
                        feat[mt][nt][0] = v0; feat[mt][nt][1] = v1;
                        feat[mt][nt][2] = v2; feat[mt][nt][3] = v3;
                    } else {
                        feat[mt][nt][0] += v0; feat[mt][nt][1] += v1;
                        feat[mt][nt][2] += v2; feat[mt][nt][3] += v3;
                    }
                }
            }
        }

        // ---- MLP A fragments: feat (k16 x2) + vol (k8) ----
        unsigned aM[2][2][4], aMv[2][2];
        const unsigned* vst = (const unsigned*)(smem + VST_OFF + warp*512);
#pragma unroll
        for (int mt = 0; mt < 2; mt++) {
#pragma unroll
            for (int kt = 0; kt < 2; kt++) {
                aM[mt][kt][0] = packh2(feat[mt][2*kt][0],   feat[mt][2*kt][1]);
                aM[mt][kt][1] = packh2(feat[mt][2*kt][2],   feat[mt][2*kt][3]);
                aM[mt][kt][2] = packh2(feat[mt][2*kt+1][0], feat[mt][2*kt+1][1]);
                aM[mt][kt][3] = packh2(feat[mt][2*kt+1][2], feat[mt][2*kt+1][3]);
            }
            aMv[mt][0] = vst[(mt*16 + g)*4 + t];
            aMv[mt][1] = vst[(mt*16 + g + 8)*4 + t];
        }

        // ---- MLP MMAs + fused relu + W2 dot ----
        float s0[2] = {0.f, 0.f}, s1[2] = {0.f, 0.f};
        const unsigned* wb1 = (const unsigned*)(smem + WB1F_OFF);
        const float* s12 = (const float*)(smem + B1W2_OFF);
#pragma unroll
        for (int nt = 0; nt < 16; nt++) {
            uint2 v0 = *(const uint2*)(wb1 + ((nt*3 + 0)*32 + lane)*2);
            uint2 v1 = *(const uint2*)(wb1 + ((nt*3 + 1)*32 + lane)*2);
            unsigned bv = wb1[((nt*3 + 2)*32 + lane)*2];
            unsigned bf0[2] = { v0.x, v0.y };
            unsigned bf1[2] = { v1.x, v1.y };
            float4 f12 = *(const float4*)(s12 + (nt*8 + 2*t)*2);
#pragma unroll
            for (int mt = 0; mt < 2; mt++) {
                float c[4] = {0.f,0.f,0.f,0.f};
                mma16816(c, aM[mt][0], bf0);
                mma16816(c, aM[mt][1], bf1);
                mma16808(c, aMv[mt], bv);
                s0[mt] += fmaxf(c[0] + f12.x, 0.f)*f12.y + fmaxf(c[1] + f12.z, 0.f)*f12.w;
                s1[mt] += fmaxf(c[2] + f12.x, 0.f)*f12.y + fmaxf(c[3] + f12.z, 0.f)*f12.w;
            }
        }

        // ---- quad reduce + scatter store via original index ----
#pragma unroll
        for (int mt = 0; mt < 2; mt++) {
            s0[mt] += __shfl_xor_sync(0xffffffffu, s0[mt], 1);
            s0[mt] += __shfl_xor_sync(0xffffffffu, s0[mt], 2);
            s1[mt] += __shfl_xor_sync(0xffffffffu, s1[mt], 1);
            s1[mt] += __shfl_xor_sync(0xffffffffu, s1[mt], 2);
        }
#pragma unroll
        for (int mt = 0; mt < 2; mt++) {
            int r0 = mt*16 + g, r1 = r0 + 8;
            int i0 = __shfl_sync(0xffffffffu, oidx, r0);
            int i1 = __shfl_sync(0xffffffffu, oidx, r1);
            if (t == 0) {
                if (tile0 + r0 < M) out[i0] = s0[mt] + bias2;
                if (tile0 + r1 < M) out[i1] = s1[mt] + bias2;
            }
        }
        __syncwarp();
    }
}

// ---------------- launch ----------------
extern "C" void kernel_launch(void* const* d_in, const int* in_sizes, int n_in,
                              void* d_out, int out_size)
{
    const float* coords = (const float*)d_in[0];
    const float* lx  = (const float*)d_in[1];
    const float* ly  = (const float*)d_in[2];
    const float* lz  = (const float*)d_in[3];
    const float* pxy = (const float*)d_in[4];
    const float* pyz = (const float*)d_in[5];
    const float* pxz = (const float*)d_in[6];
    const float* vol = (const float*)d_in[7];
    const float* Wx  = (const float*)d_in[8];
    const float* bx  = (const float*)d_in[9];
    const float* Wy  = (const float*)d_in[10];
    const float* by  = (const float*)d_in[11];
    const float* Wz  = (const float*)d_in[12];
    const float* bz  = (const float*)d_in[13];
    const float* W1  = (const float*)d_in[14];
    const float* b1  = (const float*)d_in[15];
    const float* W2  = (const float*)d_in[16];
    const float* b2  = (const float*)d_in[17];
    float* out = (float*)d_out;

    int M = in_sizes[0] / 3;
    int use_sorted = (M > 0 && M <= PCAP) ? 1 : 0;
    int gp = (M + 255) / 256;

    cudaFuncSetAttribute(k_main, cudaFuncAttributeMaxDynamicSharedMemorySize, SMEM_BYTES);

    if (use_sorted) {
        // g_cnt arrives zeroed: static zero-init on first run, re-zeroed by k_scanC each replay
        k_prep<<<1536 + 2048 + gp, 256>>>(pxy, pyz, pxz, vol, coords, M);
        k_scanA<<<256, 256>>>();
        k_scanC<<<256, 256>>>();
        k_scatter<<<(M + 511) / 512, 256>>>(coords, M);
    } else {
        k_prep<<<1536 + 2048, 256>>>(pxy, pyz, pxz, vol, coords, 0);
    }

    int grid = min(296, gp);
    k_main<<<grid, 256, SMEM_BYTES>>>(coords, use_sorted, lx, ly, lz,
                                      Wx, bx, Wy, by, Wz, bz,
                                      W1, b1, W2, b2, out, M);
}

// round 17
// speedup vs baseline: 1.1988x; 1.0543x over previous
#include <cuda_runtime.h>
#include <cuda_fp16.h>
#include <cstdint>

#define PSZ (128*128*32)
#define VSZ (64*64*64*8)
#define PCAP (1<<20)          // max points supported by sort path
#define NB   262144           // 64^3 morton buckets

// device scratch
__device__ __align__(128) __half g_plane_h[3*PSZ];   // [p][(row*128+col)*32 + c]
__device__ __align__(128) __half g_vol_h[VSZ];       // [((z*64+y)*64+x)*8 + c]
__device__ __align__(128) float4 g_pts[PCAP];        // sorted (x,y,z,orig_idx)
__device__ unsigned g_cnt[NB];                       // zero-init; re-zeroed by k_scanC
__device__ unsigned g_cnt2[NB];
__device__ unsigned g_bsum[256];

// ---------------- smem byte layout (k_main, 512 threads / 16 warps, 1 CTA/SM) ----------------
#define ESTG_OFF  0                    // 16 warps * 2560B plane staging (32 rows x 80B)
#define LINES_OFF 40960                // 3 * 128 * 80B (40 halves/row, 32 used)
#define WBF_OFF   71680                // 3ax*4nt*2kt*32lane*2 uints = 6144B (768 slots)
#define WB1F_OFF  77824                // 16nt*3kt*32lane*2 uints = 12288B (1536 slots)
#define VST_OFF   90112                // 16 warps * 32 lanes * 16B = 8192B
#define B1W2_OFF  98304                // 128 * (b1,W2) interleaved f32 = 1024B
#define BAX_OFF   99328                // 3*32 f32 = 384B
#define SMEM_BYTES 99712

// ---------------- morton bucket (64^3, 18-bit) ----------------
__device__ __forceinline__ unsigned mpart(unsigned v)
{
    v &= 0x3FF;
    v = (v | (v << 16)) & 0x030000FF;
    v = (v | (v << 8))  & 0x0300F00F;
    v = (v | (v << 4))  & 0x030C30C3;
    v = (v | (v << 2))  & 0x09249249;
    return v;
}
__device__ __forceinline__ unsigned bucket_of(float x, float y, float z)
{
    unsigned bx = (unsigned)min(max((int)((x + 1.f) * 32.f), 0), 63);
    unsigned by = (unsigned)min(max((int)((y + 1.f) * 32.f), 0), 63);
    unsigned bz = (unsigned)min(max((int)((z + 1.f) * 32.f), 0), 63);
    return mpart(bx) | (mpart(by) << 1) | (mpart(bz) << 2);   // 18-bit morton
}

// ---------------- merged preprocessing (transpose + histogram) ----------------
__global__ void k_prep(const float* __restrict__ pxy, const float* __restrict__ pyz,
                       const float* __restrict__ pxz, const float* __restrict__ vol,
                       const float* __restrict__ coords, int M)
{
    int tid = threadIdx.x;
    if (blockIdx.x < 1536) {
        __shared__ float tile[32][33];
        int p   = blockIdx.x >> 9;
        int hw0 = (blockIdx.x & 511) * 32;
        const float* src = (p == 0) ? pxy : (p == 1) ? pyz : pxz;
        __half* dst = g_plane_h + p * PSZ;
        int tx = tid & 31, ty = tid >> 5;
        #pragma unroll
        for (int cc = ty; cc < 32; cc += 8)
            tile[cc][tx] = src[cc * 16384 + hw0 + tx];
        __syncthreads();
        #pragma unroll
        for (int hwL = ty; hwL < 32; hwL += 8)
            dst[(hw0 + hwL) * 32 + tx] = __float2half(tile[tx][hwL]);
    } else if (blockIdx.x < 1536 + 2048) {
        __shared__ float t[8][129];
        int vox0 = (blockIdx.x - 1536) * 128;
        int w = tid >> 5, lane = tid & 31;
        #pragma unroll
        for (int j = lane; j < 128; j += 32)
            t[w][j] = vol[w * 262144 + vox0 + j];
        __syncthreads();
        #pragma unroll
        for (int rep = 0; rep < 4; rep++) {
            int idx = rep * 256 + tid;
            int v = idx >> 3, c = idx & 7;
            g_vol_h[vox0 * 8 + idx] = __float2half(t[c][v]);
        }
    } else {
        int m = (blockIdx.x - (1536 + 2048)) * 256 + tid;
        if (m < M)
            atomicAdd(&g_cnt[bucket_of(coords[3*m], coords[3*m+1], coords[3*m+2])], 1u);
    }
}

// ---------------- 2-stage parallel scan of 262144 buckets ----------------
__global__ void k_scanA()
{
    __shared__ unsigned red[256];
    int b = blockIdx.x, t = threadIdx.x;
    uint4 v = *(const uint4*)&g_cnt[b*1024 + t*4];
    red[t] = v.x + v.y + v.z + v.w;
    __syncthreads();
    for (int d = 128; d > 0; d >>= 1) {
        if (t < d) red[t] += red[t + d];
        __syncthreads();
    }
    if (t == 0) g_bsum[b] = red[0];
}

__global__ void k_scanC()
{
    __shared__ unsigned ss[256];
    __shared__ unsigned pre[256];
    int b = blockIdx.x, t = threadIdx.x;

    pre[t] = (t < b) ? g_bsum[t] : 0u;
    uint4 v = *(const uint4*)&g_cnt[b*1024 + t*4];
    unsigned s = v.x + v.y + v.z + v.w;
    ss[t] = s;
    __syncthreads();
    for (int d = 128; d > 0; d >>= 1) {
        if (t < d) pre[t] += pre[t + d];
        __syncthreads();
    }
    unsigned blk_off = pre[0];
    __syncthreads();
    for (int d = 1; d < 256; d <<= 1) {
        unsigned add = (t >= d) ? ss[t - d] : 0u;
        __syncthreads();
        ss[t] += add;
        __syncthreads();
    }
    unsigned excl = ss[t] - s + blk_off;
    uint4 o;
    o.x = excl;
    o.y = excl + v.x;
    o.z = excl + v.x + v.y;
    o.w = excl + v.x + v.y + v.z;
    *(uint4*)&g_cnt2[b*1024 + t*4] = o;

    uint4 z = make_uint4(0u, 0u, 0u, 0u);
    *(uint4*)&g_cnt[b*1024 + t*4] = z;
}

__global__ void k_scatter(const float* __restrict__ coords, int M)
{
    int m = blockIdx.x * 256 + threadIdx.x;
    if (m >= M) return;
    float x = coords[3*m], y = coords[3*m+1], z = coords[3*m+2];
    unsigned pos = atomicAdd(&g_cnt2[bucket_of(x, y, z)], 1u);
    __stcs(&g_pts[pos], make_float4(x, y, z, __int_as_float(m)));
}

// ---------------- warp MMA helpers ----------------
__device__ __forceinline__ void mma16816(float c[4], const unsigned a[4], const unsigned b[2])
{
    asm volatile("mma.sync.aligned.m16n8k16.row.col.f32.f16.f16.f32 "
        "{%0,%1,%2,%3}, {%4,%5,%6,%7}, {%8,%9}, {%0,%1,%2,%3};\n"
        : "+f"(c[0]), "+f"(c[1]), "+f"(c[2]), "+f"(c[3])
        : "r"(a[0]), "r"(a[1]), "r"(a[2]), "r"(a[3]), "r"(b[0]), "r"(b[1]));
}
__device__ __forceinline__ void mma16808(float c[4], const unsigned a[2], unsigned b)
{
    asm volatile("mma.sync.aligned.m16n8k8.row.col.f32.f16.f16.f32 "
        "{%0,%1,%2,%3}, {%4,%5}, {%6}, {%0,%1,%2,%3};\n"
        : "+f"(c[0]), "+f"(c[1]), "+f"(c[2]), "+f"(c[3])
        : "r"(a[0]), "r"(a[1]), "r"(b));
}
__device__ __forceinline__ void ldsm4(unsigned r[4], unsigned addr)
{
    asm volatile("ldmatrix.sync.aligned.m8n8.x4.shared.b16 {%0,%1,%2,%3}, [%4];"
        : "=r"(r[0]), "=r"(r[1]), "=r"(r[2]), "=r"(r[3]) : "r"(addr));
}
__device__ __forceinline__ unsigned packh2(float a, float b)
{
    __half2 h = __floats2half2_rn(a, b);
    return *(unsigned*)&h;
}

// ---------------- main fused kernel: persistent, 512 threads, 1 CTA/SM ----------------
__global__ void __launch_bounds__(512, 1) k_main(
    const float* __restrict__ coords, int use_sorted,
    const float* __restrict__ lx, const float* __restrict__ ly, const float* __restrict__ lz,
    const float* __restrict__ Wx, const float* __restrict__ bx,
    const float* __restrict__ Wy, const float* __restrict__ by,
    const float* __restrict__ Wz, const float* __restrict__ bz,
    const float* __restrict__ W1, const float* __restrict__ b1,
    const float* __restrict__ W2, const float* __restrict__ b2,
    float* __restrict__ out, int M)
{
    extern __shared__ char smem[];
    int tid = threadIdx.x;

    // ---- one-time smem init ----
    {
        __half* Lh = (__half*)(smem + LINES_OFF);
        for (int i = tid; i < 3*4096; i += 512) {
            int ax = i >> 12, r = i & 4095, pos = r >> 5, c = r & 31;
            const float* s = (ax == 0) ? lx : (ax == 1) ? ly : lz;
            Lh[ax*5120 + pos*40 + c] = __float2half(s[c*128 + pos]);
        }
    }
    {
        // 768 slots exactly: 3ax * 4nt * 2kt * 32lane  (BUGFIX: was 1536 — the
        // extra range decoded ax∈{3,4,5} and overflowed into the WB1F region)
        unsigned* wb = (unsigned*)(smem + WBF_OFF);
        for (int i = tid; i < 768; i += 512) {
            int ax = i >> 8, r = i & 255;
            int nt = r >> 6, r2 = r & 63, kt = r2 >> 5, ln = r2 & 31;
            int gg = ln >> 2, tt = ln & 3;
            int n = nt*8 + gg, k0 = kt*16 + 2*tt;
            const float* W = (ax == 0) ? Wx : (ax == 1) ? Wy : Wz;
            wb[i*2 + 0] = packh2(W[k0*32 + n],     W[(k0+1)*32 + n]);
            wb[i*2 + 1] = packh2(W[(k0+8)*32 + n], W[(k0+9)*32 + n]);
        }
    }
    {
        unsigned* wb = (unsigned*)(smem + WB1F_OFF);
        for (int i = tid; i < 1536; i += 512) {
            int nt = i / 96, r = i - nt*96, kt = r >> 5, ln = r & 31;
            int gg = ln >> 2, tt = ln & 3;
            int n = nt*8 + gg, k0 = kt*16 + 2*tt;
            float v0 = (k0   < 40) ? W1[(k0  )*128 + n] : 0.f;
            float v1 = (k0+1 < 40) ? W1[(k0+1)*128 + n] : 0.f;
            float v2 = (k0+8 < 40) ? W1[(k0+8)*128 + n] : 0.f;
            float v3 = (k0+9 < 40) ? W1[(k0+9)*128 + n] : 0.f;
            wb[i*2 + 0] = packh2(v0, v1);
            wb[i*2 + 1] = packh2(v2, v3);
        }
    }
    {
        float* ba = (float*)(smem + BAX_OFF);
        for (int i = tid; i < 96; i += 512)
            ba[i] = (i < 32) ? bx[i] : (i < 64) ? by[i-32] : bz[i-64];
        float* s12 = (float*)(smem + B1W2_OFF);
        for (int i = tid; i < 128; i += 512) {
            s12[i*2 + 0] = b1[i];
            s12[i*2 + 1] = W2[i];
        }
    }
    __syncthreads();

    int lane = tid & 31, warp = tid >> 5;       // warp 0..15
    int g = lane >> 2, t = lane & 3;
    const __half2 z2 = __float2half2_rn(0.f);

    char* eS_base = smem + ESTG_OFF + warp*2560;
    unsigned sbase = (unsigned)__cvta_generic_to_shared(smem);
    unsigned eS_u = sbase + ESTG_OFF + warp*2560;
    int rowpart = (lane & 15)*80 + ((lane >> 4) << 4);
    int lrow = lane & 15;
    int lcolh = (lane >> 4) << 4;
    float bias2 = b2[0];

    int nblk = (M + 511) >> 9;                  // 512-point CTA blocks

    for (int blk = blockIdx.x; blk < nblk; blk += gridDim.x) {
        int tile0 = blk * 512 + warp * 32;
        int m  = tile0 + lane;
        int mc = min(m, M - 1);

        float x, y, z;
        int oidx;
        if (use_sorted) {
            float4 p = __ldcs(&g_pts[mc]);
            x = p.x; y = p.y; z = p.z;
            oidx = __float_as_int(p.w);
        } else {
            x = coords[3*mc + 0];
            y = coords[3*mc + 1];
            z = coords[3*mc + 2];
            oidx = mc;
        }

        float fx = (x + 1.f) * (0.5f * 127.f);
        float fy = (y + 1.f) * (0.5f * 127.f);
        float fz = (z + 1.f) * (0.5f * 127.f);
        float fix = fminf(fmaxf(floorf(fx), 0.f), 126.f);
        float fiy = fminf(fmaxf(floorf(fy), 0.f), 126.f);
        float fiz = fminf(fmaxf(floorf(fz), 0.f), 126.f);
        int ix = (int)fix, iy = (int)fiy, iz = (int)fiz;
        float wxp = fx - fix, wyp = fy - fiy, wzp = fz - fiz;

        float gx = (x + 1.f) * (0.5f * 63.f);
        float gy = (y + 1.f) * (0.5f * 63.f);
        float gz = (z + 1.f) * (0.5f * 63.f);
        float gvx = fminf(fmaxf(floorf(gx), 0.f), 62.f);
        float gvy = fminf(fmaxf(floorf(gy), 0.f), 62.f);
        float gvz = fminf(fmaxf(floorf(gz), 0.f), 62.f);
        int vx = (int)gvx, vy = (int)gvy, vz = (int)gvz;
        float ux = gx - gvx, uy = gy - gvy, uz = gz - gvz;

        // ---- volume trilinear -> VST ----
        {
            const uint4* vb = (const uint4*)(g_vol_h + ((((vz*64 + vy)*64) + vx) << 3));
            float iux = 1.f - ux, iuy = 1.f - uy, iuz = 1.f - uz;
            __half2 va0 = z2, va1 = z2, va2 = z2, va3 = z2;
#pragma unroll
            for (int corner = 0; corner < 8; corner++) {
                int dx = corner & 1, dy = (corner >> 1) & 1, dz = corner >> 2;
                float wgt = (dx ? ux : iux) * (dy ? uy : iuy) * (dz ? uz : iuz);
                __half2 w2 = __float2half2_rn(wgt);
                uint4 T = vb[dx + dy*64 + dz*4096];
                const __half2* th = (const __half2*)&T;
                va0 = __hfma2(w2, th[0], va0);
                va1 = __hfma2(w2, th[1], va1);
                va2 = __hfma2(w2, th[2], va2);
                va3 = __hfma2(w2, th[3], va3);
            }
            uint4* vr = (uint4*)(smem + VST_OFF + warp*512 + lane*16);
            uint4 o;
            o.x = *(unsigned*)&va0; o.y = *(unsigned*)&va1;
            o.z = *(unsigned*)&va2; o.w = *(unsigned*)&va3;
            *vr = o;
        }

        int ixs[3] = { ix, iy, iz };
        float wls[3] = { wxp, wyp, wzp };
        const __half* plb[3] = { g_plane_h + PSZ, g_plane_h + 2*PSZ, g_plane_h };
        int pcol[3] = { iy, ix, ix };
        int prow[3] = { iz, iz, iy };
        float pwc[3] = { wyp, wxp, wxp };
        float pwr[3] = { wzp, wzp, wyp };

        float feat[2][4][4];

#pragma unroll
        for (int ax = 0; ax < 3; ax++) {
            unsigned aL[2][2][4], aP[2][2][4];

            // ---- plane sample (issues LDGs early) -> staging rows ----
            {
                const uint4* t00 = (const uint4*)(plb[ax] + (size_t)(prow[ax]*128 + pcol[ax])*32);
                const uint4* t01 = t00 + 4;
                const uint4* t10 = t00 + 512;
                const uint4* t11 = t10 + 4;
                float wc = pwc[ax], wr = pwr[ax];
                float iwc = 1.f - wc, iwr = 1.f - wr;
                __half2 w00 = __float2half2_rn(iwc*iwr);
                __half2 w01 = __float2half2_rn( wc*iwr);
                __half2 w10 = __float2half2_rn(iwc* wr);
                __half2 w11 = __float2half2_rn( wc* wr);
                uint4* dst = (uint4*)(eS_base + lane*80);
#pragma unroll
                for (int h = 0; h < 4; h++) {
                    uint4 A = t00[h], B = t01[h], C = t10[h], D = t11[h];
                    const __half2* a = (const __half2*)&A;
                    const __half2* b = (const __half2*)&B;
                    const __half2* c = (const __half2*)&C;
                    const __half2* d = (const __half2*)&D;
                    uint4 o;
                    unsigned* oh = (unsigned*)&o;
#pragma unroll
                    for (int k = 0; k < 4; k++) {
                        __half2 acc = __hmul2(w00, a[k]);
                        __half2 ac2 = __hmul2(w01, b[k]);
                        acc = __hfma2(w10, c[k], acc);
                        ac2 = __hfma2(w11, d[k], ac2);
                        acc = __hadd2(acc, ac2);
                        acc = __hmax2(acc, z2);
                        oh[k] = *(unsigned*)&acc;
                    }
                    dst[h] = o;
                }
            }

            // ---- line A-fragments direct from LINES via ldmatrix ----
            {
                unsigned lines_u = sbase + LINES_OFF + ax*10240;
#pragma unroll
                for (int mt = 0; mt < 2; mt++) {
                    int   ixv = __shfl_sync(0xffffffffu, ixs[ax], mt*16 + lrow);
                    float wA  = __shfl_sync(0xffffffffu, wls[ax], mt*16 + g);
                    float wB  = __shfl_sync(0xffffffffu, wls[ax], mt*16 + g + 8);
                    __half2 wA2 = __float2half2_rn(wA);
                    __half2 wB2 = __float2half2_rn(wB);
                    unsigned base0 = lines_u + ixv*80 + lcolh;
#pragma unroll
                    for (int kt = 0; kt < 2; kt++) {
                        unsigned r0[4], r1[4];
                        ldsm4(r0, base0 + kt*32);
                        ldsm4(r1, base0 + 80 + kt*32);
#pragma unroll
                        for (int j = 0; j < 4; j++) {
                            __half2 l0 = *(__half2*)&r0[j];
                            __half2 l1 = *(__half2*)&r1[j];
                            __half2 w2 = (j & 1) ? wB2 : wA2;
                            __half2 e  = __hfma2(w2, __hsub2(l1, l0), l0);
                            e = __hmax2(e, z2);
                            aL[mt][kt][j] = *(unsigned*)&e;
                        }
                    }
                }
            }

            __syncwarp();
#pragma unroll
            for (int mt = 0; mt < 2; mt++)
#pragma unroll
            for (int kt = 0; kt < 2; kt++)
                ldsm4(aP[mt][kt], eS_u + mt*16*80 + kt*32 + rowpart);
            __syncwarp();

            const unsigned* wb = (const unsigned*)(smem + WBF_OFF) + ax*512;
            const float* ba = (const float*)(smem + BAX_OFF) + ax*32;
#pragma unroll
            for (int nt = 0; nt < 4; nt++) {
                uint2 bfa = *(const uint2*)(wb + ((nt*2+0)*32 + lane)*2);
                uint2 bfb = *(const uint2*)(wb + ((nt*2+1)*32 + lane)*2);
                unsigned bf0[2] = { bfa.x, bfa.y };
                unsigned bf1[2] = { bfb.x, bfb.y };
                float2 bb = *(const float2*)(ba + nt*8 + 2*t);
#pragma unroll
                for (int mt = 0; mt < 2; mt++) {
                    float tl[4] = {0.f,0.f,0.f,0.f};
                    float tp[4] = {0.f,0.f,0.f,0.f};
                    mma16816(tl, aL[mt][0], bf0);
                    mma16816(tl, aL[mt][1], bf1);
                    mma16816(tp, aP[mt][0], bf0);
                    mma16816(tp, aP[mt][1], bf1);
                    float v0 = (tl[0] + bb.x) * (tp[0] + bb.x);
                    float v1 = (tl[1] + bb.y) * (tp[1] + bb.y);
                    float v2 = (tl[2] + bb.x) * (tp[2] + bb.x);
                    float v3 = (tl[3] + bb.y) * (tp[3] + bb.y);
                    if (ax == 0) {
                        feat[mt][nt][0] = v0; feat[mt][nt][1] = v1;
                        feat[mt][nt][2] = v2; feat[mt][nt][3] = v3;
                    } else {
                        feat[mt][nt][0] += v0; feat[mt][nt][1] += v1;
                        feat[mt][nt][2] += v2; feat[mt][nt][3] += v3;
                    }
                }
            }
        }

        // ---- MLP A fragments: feat (k16 x2) + vol (k8) ----
        unsigned aM[2][2][4], aMv[2][2];
        const unsigned* vst = (const unsigned*)(smem + VST_OFF + warp*512);
#pragma unroll
        for (int mt = 0; mt < 2; mt++) {
#pragma unroll
            for (int kt = 0; kt < 2; kt++) {
                aM[mt][kt][0] = packh2(feat[mt][2*kt][0],   feat[mt][2*kt][1]);
                aM[mt][kt][1] = packh2(feat[mt][2*kt][2],   feat[mt][2*kt][3]);
                aM[mt][kt][2] = packh2(feat[mt][2*kt+1][0], feat[mt][2*kt+1][1]);
                aM[mt][kt][3] = packh2(feat[mt][2*kt+1][2], feat[mt][2*kt+1][3]);
            }
            aMv[mt][0] = vst[(mt*16 + g)*4 + t];
            aMv[mt][1] = vst[(mt*16 + g + 8)*4 + t];
        }

        // ---- MLP MMAs + fused relu + W2 dot ----
        float s0[2] = {0.f, 0.f}, s1[2] = {0.f, 0.f};
        const unsigned* wb1 = (const unsigned*)(smem + WB1F_OFF);
        const float* s12 = (const float*)(smem + B1W2_OFF);
#pragma unroll
        for (int nt = 0; nt < 16; nt++) {
            uint2 v0 = *(const uint2*)(wb1 + ((nt*3 + 0)*32 + lane)*2);
            uint2 v1 = *(const uint2*)(wb1 + ((nt*3 + 1)*32 + lane)*2);
            unsigned bv = wb1[((nt*3 + 2)*32 + lane)*2];
            unsigned bf0[2] = { v0.x, v0.y };
            unsigned bf1[2] = { v1.x, v1.y };
            float4 f12 = *(const float4*)(s12 + (nt*8 + 2*t)*2);
#pragma unroll
            for (int mt = 0; mt < 2; mt++) {
                float c[4] = {0.f,0.f,0.f,0.f};
                mma16816(c, aM[mt][0], bf0);
                mma16816(c, aM[mt][1], bf1);
                mma16808(c, aMv[mt], bv);
                s0[mt] += fmaxf(c[0] + f12.x, 0.f)*f12.y + fmaxf(c[1] + f12.z, 0.f)*f12.w;
                s1[mt] += fmaxf(c[2] + f12.x, 0.f)*f12.y + fmaxf(c[3] + f12.z, 0.f)*f12.w;
            }
        }

        // ---- quad reduce + scatter store via original index ----
#pragma unroll
        for (int mt = 0; mt < 2; mt++) {
            s0[mt] += __shfl_xor_sync(0xffffffffu, s0[mt], 1);
            s0[mt] += __shfl_xor_sync(0xffffffffu, s0[mt], 2);
            s1[mt] += __shfl_xor_sync(0xffffffffu, s1[mt], 1);
            s1[mt] += __shfl_xor_sync(0xffffffffu, s1[mt], 2);
        }
#pragma unroll
        for (int mt = 0; mt < 2; mt++) {
            int r0 = mt*16 + g, r1 = r0 + 8;
            int i0 = __shfl_sync(0xffffffffu, oidx, r0);
            int i1 = __shfl_sync(0xffffffffu, oidx, r1);
            if (t == 0) {
                if (tile0 + r0 < M) out[i0] = s0[mt] + bias2;
                if (tile0 + r1 < M) out[i1] = s1[mt] + bias2;
            }
        }
        __syncwarp();
    }
}

// ---------------- launch ----------------
extern "C" void kernel_launch(void* const* d_in, const int* in_sizes, int n_in,
                              void* d_out, int out_size)
{
    const float* coords = (const float*)d_in[0];
    const float* lx  = (const float*)d_in[1];
    const float* ly  = (const float*)d_in[2];
    const float* lz  = (const float*)d_in[3];
    const float* pxy = (const float*)d_in[4];
    const float* pyz = (const float*)d_in[5];
    const float* pxz = (const float*)d_in[6];
    const float* vol = (const float*)d_in[7];
    const float* Wx  = (const float*)d_in[8];
    const float* bx  = (const float*)d_in[9];
    const float* Wy  = (const float*)d_in[10];
    const float* by  = (const float*)d_in[11];
    const float* Wz  = (const float*)d_in[12];
    const float* bz  = (const float*)d_in[13];
    const float* W1  = (const float*)d_in[14];
    const float* b1  = (const float*)d_in[15];
    const float* W2  = (const float*)d_in[16];
    const float* b2  = (const float*)d_in[17];
    float* out = (float*)d_out;

    int M = in_sizes[0] / 3;
    int use_sorted = (M > 0 && M <= PCAP) ? 1 : 0;
    int gp = (M + 255) / 256;

    cudaFuncSetAttribute(k_main, cudaFuncAttributeMaxDynamicSharedMemorySize, SMEM_BYTES);

    if (use_sorted) {
        // g_cnt arrives zeroed: static zero-init on first run, re-zeroed by k_scanC each replay
        k_prep<<<1536 + 2048 + gp, 256>>>(pxy, pyz, pxz, vol, coords, M);
        k_scanA<<<256, 256>>>();
        k_scanC<<<256, 256>>>();
        k_scatter<<<gp, 256>>>(coords, M);
    } else {
        k_prep<<<1536 + 2048, 256>>>(pxy, pyz, pxz, vol, coords, 0);
    }

    int nblk512 = (M + 511) / 512;
    int grid = min(152, nblk512);           // GB300: 152 SMs
    k_main<<<grid, 512, SMEM_BYTES>>>(coords, use_sorted, lx, ly, lz,
                                      Wx, bx, Wy, by, Wz, bz,
                                      W1, b1, W2, b2, out, M);
}